// round 4
// baseline (speedup 1.0000x reference)
#include <cuda_runtime.h>
#include <cstdint>

// out(b, y, x) = bilinear sample of img_b at (y + 5 + py, x + 5 + px), zero
// outside [0, 522). One thread per output pixel, lane-consecutive in x for
// fully coalesced loads/stores. Predicated __ldg for the 4 taps (no memory
// access when predicate false, so OOB pointers are never dereferenced).

static constexpr int NPAD = 522;   // padded input H = W
static constexpr int NOUT = 512;   // output H = W
static constexpr int B    = 256;

__global__ __launch_bounds__(256) void extract_patches_kernel(
    const float* __restrict__ img,   // (B, 522, 522, 1)
    const float* __restrict__ pos,   // (B, 2)  [px, py]
    float* __restrict__ out)         // (B, 512, 512, 1)
{
    const int b = blockIdx.z;
    const int y = blockIdx.y;
    const int x = blockIdx.x * blockDim.x + threadIdx.x;

    const float px = __ldg(pos + 2 * b);
    const float py = __ldg(pos + 2 * b + 1);

    // Match reference fp32 arithmetic exactly: arange(H) + offset, then floor.
    const float sy  = (float)(y + 5) + py;
    const float y0f = floorf(sy);
    const float wy  = sy - y0f;
    const int   Y   = (int)y0f;

    const float sx  = (float)(x + 5) + px;
    const float x0f = floorf(sx);
    const float wx  = sx - x0f;
    const int   X   = (int)x0f;

    const bool vy0 = ((unsigned)Y       < (unsigned)NPAD);
    const bool vy1 = ((unsigned)(Y + 1) < (unsigned)NPAD);
    const bool vx0 = ((unsigned)X       < (unsigned)NPAD);
    const bool vx1 = ((unsigned)(X + 1) < (unsigned)NPAD);

    const float* base = img + (size_t)b * (NPAD * NPAD);
    const float* r0 = base + (ptrdiff_t)Y * NPAD;
    const float* r1 = r0 + NPAD;

    const float g00 = (vy0 && vx0) ? __ldg(r0 + X)     : 0.0f;
    const float g01 = (vy0 && vx1) ? __ldg(r0 + X + 1) : 0.0f;
    const float g10 = (vy1 && vx0) ? __ldg(r1 + X)     : 0.0f;
    const float g11 = (vy1 && vx1) ? __ldg(r1 + X + 1) : 0.0f;

    const float top = g00 * (1.0f - wx) + g01 * wx;
    const float bot = g10 * (1.0f - wx) + g11 * wx;
    const float val = top * (1.0f - wy) + bot * wy;

    out[((size_t)b * NOUT + y) * NOUT + x] = val;
}

extern "C" void kernel_launch(void* const* d_in, const int* in_sizes, int n_in,
                              void* d_out, int out_size)
{
    const float* img = (const float*)d_in[0];   // padded_obj: 256*522*522*1 f32
    const float* pos = (const float*)d_in[1];   // positions:  256*2 f32
    float* out = (float*)d_out;                 // 256*512*512*1 f32

    dim3 block(256, 1, 1);
    dim3 grid(NOUT / 256, NOUT, B);             // (2, 512, 256)
    extract_patches_kernel<<<grid, block>>>(img, pos, out);
}

// round 5
// speedup vs baseline: 1.8956x; 1.8956x over previous
#include <cuda_runtime.h>
#include <cstdint>

// out(b, y, x) = bilinear sample of img_b at (y + 5 + py, x + 5 + px), zero
// outside [0, 522).
// 4 pixels per thread, strided by 128 so each chunk's lanes are consecutive
// in x (1 cache line per warp-LDG). Row-side arithmetic (sy, floor, Y, row
// validity, row base pointer) is computed once per thread and shared by all
// 4 pixels; the 16 tap loads are independent -> MLP≈16.

static constexpr int NPAD = 522;   // padded input H = W
static constexpr int NOUT = 512;   // output H = W
static constexpr int B    = 256;

__global__ __launch_bounds__(128) void extract_patches_kernel(
    const float* __restrict__ img,   // (B, 522, 522, 1)
    const float* __restrict__ pos,   // (B, 2)  [px, py]
    float* __restrict__ out)         // (B, 512, 512, 1)
{
    const int b   = blockIdx.z;
    const int y   = blockIdx.y;
    const int tid = threadIdx.x;

    const float px = __ldg(pos + 2 * b);
    const float py = __ldg(pos + 2 * b + 1);

    // Per-row work: once per thread (matches reference fp32 op order).
    const float sy  = (float)(y + 5) + py;
    const float y0f = floorf(sy);
    const float wy  = sy - y0f;
    const int   Y   = (int)y0f;

    const bool vy0 = ((unsigned)Y       < (unsigned)NPAD);
    const bool vy1 = ((unsigned)(Y + 1) < (unsigned)NPAD);

    const float* r0   = img + (size_t)b * (NPAD * NPAD) + (ptrdiff_t)Y * NPAD;
    float*       orow = out + ((size_t)b * NOUT + y) * NOUT;

    #pragma unroll
    for (int c = 0; c < 4; c++) {
        const int   x   = tid + c * 128;
        const float sx  = (float)(x + 5) + px;
        const float x0f = floorf(sx);
        const float wx  = sx - x0f;
        const int   X   = (int)x0f;

        const bool vx0 = ((unsigned)X       < (unsigned)NPAD);
        const bool vx1 = ((unsigned)(X + 1) < (unsigned)NPAD);

        const float* p0 = r0 + X;
        float g00 = 0.0f, g01 = 0.0f, g10 = 0.0f, g11 = 0.0f;
        if (vy0 && vx0) g00 = __ldg(p0);
        if (vy0 && vx1) g01 = __ldg(p0 + 1);
        if (vy1 && vx0) g10 = __ldg(p0 + NPAD);
        if (vy1 && vx1) g11 = __ldg(p0 + NPAD + 1);

        // top = g00*(1-wx) + g01*wx, regrouped to FADD+FFMA pairs.
        const float top = g00 + wx * (g01 - g00);
        const float bot = g10 + wx * (g11 - g10);
        orow[x] = top + wy * (bot - top);
    }
}

extern "C" void kernel_launch(void* const* d_in, const int* in_sizes, int n_in,
                              void* d_out, int out_size)
{
    const float* img = (const float*)d_in[0];   // padded_obj: 256*522*522*1 f32
    const float* pos = (const float*)d_in[1];   // positions:  256*2 f32
    float* out = (float*)d_out;                 // 256*512*512*1 f32

    dim3 block(128, 1, 1);
    dim3 grid(1, NOUT, B);                      // (1, 512, 256)
    extract_patches_kernel<<<grid, block>>>(img, pos, out);
}

// round 6
// speedup vs baseline: 1.9561x; 1.0319x over previous
#include <cuda_runtime.h>
#include <cstdint>

// out(b, y, x) = bilinear sample of img_b at (y + 5 + py, x + 5 + px), zero
// outside [0, 522). 4 pixels/thread, 128-strided (lane-consecutive chunks).
//
// Fast path (uniform per block): when floor(5+px) in [0,9] and the source row
// pair is fully inside, the integer column offset and fractional weight are
// hoisted out of x: X(x) = x + X0, wx = frac(5+px). All taps are in bounds,
// so the inner loop is pure LDG(imm offset) + FMA + STG with zero per-pixel
// integer work. Coordinate deviation from the reference's per-pixel
// fl((x+5)+px) is <= ~1.6e-5 px -> output deviation ~1e-4 abs worst-case,
// far inside the 1e-3 tolerance.
//
// Slow path (rare rows, |offset| >= ~5): exact per-pixel floor + predicated
// taps (the proven R4 code path).

static constexpr int NPAD = 522;
static constexpr int NOUT = 512;
static constexpr int B    = 256;

__global__ __launch_bounds__(128) void extract_patches_kernel(
    const float* __restrict__ img,   // (B, 522, 522, 1)
    const float* __restrict__ pos,   // (B, 2)  [px, py]
    float* __restrict__ out)         // (B, 512, 512, 1)
{
    const int b   = blockIdx.z;
    const int y   = blockIdx.y;
    const int tid = threadIdx.x;

    const float px = __ldg(pos + 2 * b);
    const float py = __ldg(pos + 2 * b + 1);

    // Row-side arithmetic (once per thread, reference fp32 op order).
    const float sy  = (float)(y + 5) + py;
    const float y0f = floorf(sy);
    const float wy  = sy - y0f;
    const int   Y   = (int)y0f;

    // Hoisted column offset/weight.
    const float s0  = 5.0f + px;
    const float x0f = floorf(s0);
    const float wx  = s0 - x0f;
    const int   X0  = (int)x0f;

    float* orow = out + ((size_t)b * NOUT + y) * NOUT;
    const float* base = img + (size_t)b * (NPAD * NPAD);

    const bool fast = (X0 >= 0) & (X0 <= 9) & (Y >= 0) & (Y <= NPAD - 2);

    if (fast) {
        // One address register; 16 loads / 4 stores via immediate offsets.
        const float* p = base + (ptrdiff_t)Y * NPAD + X0 + tid;
        #pragma unroll
        for (int c = 0; c < 4; c++) {
            const float g00 = __ldg(p + c * 128);
            const float g01 = __ldg(p + c * 128 + 1);
            const float g10 = __ldg(p + c * 128 + NPAD);
            const float g11 = __ldg(p + c * 128 + NPAD + 1);
            const float top = g00 + wx * (g01 - g00);
            const float bot = g10 + wx * (g11 - g10);
            orow[tid + c * 128] = top + wy * (bot - top);
        }
    } else {
        // Exact per-pixel path with full predication (handles zero fill).
        const bool vy0 = ((unsigned)Y       < (unsigned)NPAD);
        const bool vy1 = ((unsigned)(Y + 1) < (unsigned)NPAD);
        const float* r0 = base + (ptrdiff_t)Y * NPAD;
        #pragma unroll
        for (int c = 0; c < 4; c++) {
            const int   x    = tid + c * 128;
            const float sx   = (float)(x + 5) + px;
            const float xf   = floorf(sx);
            const float wxp  = sx - xf;
            const int   X    = (int)xf;
            const bool vx0 = ((unsigned)X       < (unsigned)NPAD);
            const bool vx1 = ((unsigned)(X + 1) < (unsigned)NPAD);
            const float* p0 = r0 + X;
            float g00 = 0.0f, g01 = 0.0f, g10 = 0.0f, g11 = 0.0f;
            if (vy0 && vx0) g00 = __ldg(p0);
            if (vy0 && vx1) g01 = __ldg(p0 + 1);
            if (vy1 && vx0) g10 = __ldg(p0 + NPAD);
            if (vy1 && vx1) g11 = __ldg(p0 + NPAD + 1);
            const float top = g00 + wxp * (g01 - g00);
            const float bot = g10 + wxp * (g11 - g10);
            orow[x] = top + wy * (bot - top);
        }
    }
}

extern "C" void kernel_launch(void* const* d_in, const int* in_sizes, int n_in,
                              void* d_out, int out_size)
{
    const float* img = (const float*)d_in[0];   // padded_obj: 256*522*522*1 f32
    const float* pos = (const float*)d_in[1];   // positions:  256*2 f32
    float* out = (float*)d_out;                 // 256*512*512*1 f32

    dim3 block(128, 1, 1);
    dim3 grid(1, NOUT, B);                      // (1, 512, 256)
    extract_patches_kernel<<<grid, block>>>(img, pos, out);
}

// round 7
// speedup vs baseline: 2.3066x; 1.1792x over previous
#include <cuda_runtime.h>
#include <cstdint>

// out(b, y, x) = bilinear sample of img_b at (y + 5 + py, x + 5 + px), zero
// outside [0, 522). 4 CONSECUTIVE pixels per thread, float4 loads/stores.
//
// Fast path (uniform per block): X(x) = x + X0, wx = frac(5+px) hoisted
// (validated in R6, rel_err ~1.2e-5). Each thread needs the 5-float span
// [c, c+4] per source row; two ALIGNED float4 loads always cover it. The
// intra-quad shift m = c & 3 is uniform across the block (c = Y*522+X0+4*tid),
// row1's shift is (m+2)&3 (522 % 4 == 2), so tap extraction is a uniform
// switch of pure register selects. Per thread: 4 LDG.128 + 1 STG.128.
//
// Slow path (rare: |offset| >= ~5, or the one last-image row pair whose
// aligned window would read past the buffer): exact per-pixel floor +
// predicated taps.

static constexpr int NPAD = 522;
static constexpr int NOUT = 512;
static constexpr int B    = 256;

__global__ __launch_bounds__(128) void extract_patches_kernel(
    const float* __restrict__ img,   // (B, 522, 522, 1)
    const float* __restrict__ pos,   // (B, 2)  [px, py]
    float* __restrict__ out)         // (B, 512, 512, 1)
{
    const int b   = blockIdx.z;
    const int y   = blockIdx.y;
    const int tid = threadIdx.x;

    const float px = __ldg(pos + 2 * b);
    const float py = __ldg(pos + 2 * b + 1);

    const float sy  = (float)(y + 5) + py;
    const float y0f = floorf(sy);
    const float wy  = sy - y0f;
    const int   Y   = (int)y0f;

    const float s0  = 5.0f + px;
    const float x0f = floorf(s0);
    const float wx  = s0 - x0f;
    const int   X0  = (int)x0f;

    const float* base = img + (size_t)b * (NPAD * NPAD);
    float*       orow = out + ((size_t)b * NOUT + y) * NOUT;

    bool fast = (X0 >= 0) & (X0 <= 9) & (Y >= 0) & (Y <= NPAD - 2);
    // Aligned window may read up to 2 floats past row Y+1's last needed
    // element; only unsafe when row Y+1 is the very last row of the buffer.
    if ((b == B - 1) & (Y == NPAD - 2)) fast = false;

    if (fast) {
        const int c0 = Y * NPAD + X0 + 4 * tid;
        const int c1 = c0 + NPAD;
        const float4 A0 = __ldg(reinterpret_cast<const float4*>(base + (c0 & ~3)));
        const float4 B0 = __ldg(reinterpret_cast<const float4*>(base + (c0 & ~3)) + 1);
        const float4 A1 = __ldg(reinterpret_cast<const float4*>(base + (c1 & ~3)));
        const float4 B1 = __ldg(reinterpret_cast<const float4*>(base + (c1 & ~3)) + 1);

        float v0, v1, v2, v3, v4;   // row Y taps  [c0 .. c0+4]
        float u0, u1, u2, u3, u4;   // row Y+1 taps [c1 .. c1+4]
        switch (c0 & 3) {           // uniform across the block
        case 0:  v0=A0.x; v1=A0.y; v2=A0.z; v3=A0.w; v4=B0.x;   // m1 = 2
                 u0=A1.z; u1=A1.w; u2=B1.x; u3=B1.y; u4=B1.z; break;
        case 1:  v0=A0.y; v1=A0.z; v2=A0.w; v3=B0.x; v4=B0.y;   // m1 = 3
                 u0=A1.w; u1=B1.x; u2=B1.y; u3=B1.z; u4=B1.w; break;
        case 2:  v0=A0.z; v1=A0.w; v2=B0.x; v3=B0.y; v4=B0.z;   // m1 = 0
                 u0=A1.x; u1=A1.y; u2=A1.z; u3=A1.w; u4=B1.x; break;
        default: v0=A0.w; v1=B0.x; v2=B0.y; v3=B0.z; v4=B0.w;   // m1 = 1
                 u0=A1.y; u1=A1.z; u2=A1.w; u3=B1.x; u4=B1.y; break;
        }

        const float t0 = v0 + wx * (v1 - v0);
        const float t1 = v1 + wx * (v2 - v1);
        const float t2 = v2 + wx * (v3 - v2);
        const float t3 = v3 + wx * (v4 - v3);
        const float q0 = u0 + wx * (u1 - u0);
        const float q1 = u1 + wx * (u2 - u1);
        const float q2 = u2 + wx * (u3 - u2);
        const float q3 = u3 + wx * (u4 - u3);

        float4 o;
        o.x = t0 + wy * (q0 - t0);
        o.y = t1 + wy * (q1 - t1);
        o.z = t2 + wy * (q2 - t2);
        o.w = t3 + wy * (q3 - t3);
        *reinterpret_cast<float4*>(orow + 4 * tid) = o;
    } else {
        // Exact per-pixel path with full predication (handles zero fill).
        const bool vy0 = ((unsigned)Y       < (unsigned)NPAD);
        const bool vy1 = ((unsigned)(Y + 1) < (unsigned)NPAD);
        const float* r0 = base + (ptrdiff_t)Y * NPAD;
        #pragma unroll
        for (int i = 0; i < 4; i++) {
            const int   x    = 4 * tid + i;
            const float sx   = (float)(x + 5) + px;
            const float xf   = floorf(sx);
            const float wxp  = sx - xf;
            const int   X    = (int)xf;
            const bool vx0 = ((unsigned)X       < (unsigned)NPAD);
            const bool vx1 = ((unsigned)(X + 1) < (unsigned)NPAD);
            const float* p0 = r0 + X;
            float g00 = 0.0f, g01 = 0.0f, g10 = 0.0f, g11 = 0.0f;
            if (vy0 && vx0) g00 = __ldg(p0);
            if (vy0 && vx1) g01 = __ldg(p0 + 1);
            if (vy1 && vx0) g10 = __ldg(p0 + NPAD);
            if (vy1 && vx1) g11 = __ldg(p0 + NPAD + 1);
            const float top = g00 + wxp * (g01 - g00);
            const float bot = g10 + wxp * (g11 - g10);
            orow[x] = top + wy * (bot - top);
        }
    }
}

extern "C" void kernel_launch(void* const* d_in, const int* in_sizes, int n_in,
                              void* d_out, int out_size)
{
    const float* img = (const float*)d_in[0];   // padded_obj: 256*522*522*1 f32
    const float* pos = (const float*)d_in[1];   // positions:  256*2 f32
    float* out = (float*)d_out;                 // 256*512*512*1 f32

    dim3 block(128, 1, 1);
    dim3 grid(1, NOUT, B);                      // (1, 512, 256)
    extract_patches_kernel<<<grid, block>>>(img, pos, out);
}

// round 9
// speedup vs baseline: 2.5942x; 1.1247x over previous
#include <cuda_runtime.h>
#include <cstdint>

// out(b, y, x) = bilinear sample of img_b at (y + 5 + py, x + 5 + px), zero
// outside [0, 522).
// TWO output rows per thread, 4 consecutive px each, float4 everywhere.
// Rows y and y+1 share source row Y+1: 3 source-row quad pairs (6 LDG.128)
// + 2 STG.128 serve 256 px. Column offset/weight hoisted (R6-validated).
// Row alignment shift: 522 % 4 == 2, so rows Y and Y+2 share shift m and
// row Y+1 uses (m+2)&3 — one uniform 4-way template dispatch, zero
// per-pixel integer work. Worst-case aligned-quad read ends exactly at the
// buffer's last element (521*522+9+508 -> &~3 +7 = 272483), so no overrun.

static constexpr int NPAD = 522;
static constexpr int NOUT = 512;
static constexpr int B    = 256;

__device__ __forceinline__ float comp(const float4& A, const float4& Bq, int i) {
    switch (i) {
    case 0: return A.x;  case 1: return A.y;  case 2: return A.z;  case 3: return A.w;
    case 4: return Bq.x; case 5: return Bq.y; case 6: return Bq.z; default: return Bq.w;
    }
}

template <int M0>
__device__ __forceinline__ void fast_pair(
    const float* __restrict__ base, float* __restrict__ o0, float* __restrict__ o1,
    int tid, int Y, int X0, float wx, float wy0, float wy1)
{
    const int c0 = Y * NPAD + X0 + 4 * tid;
    const int c1 = c0 + NPAD;
    const int c2 = c0 + 2 * NPAD;

    const float4 A0 = __ldg(reinterpret_cast<const float4*>(base + (c0 & ~3)));
    const float4 B0 = __ldg(reinterpret_cast<const float4*>(base + (c0 & ~3)) + 1);
    const float4 A1 = __ldg(reinterpret_cast<const float4*>(base + (c1 & ~3)));
    const float4 B1 = __ldg(reinterpret_cast<const float4*>(base + (c1 & ~3)) + 1);
    const float4 A2 = __ldg(reinterpret_cast<const float4*>(base + (c2 & ~3)));
    const float4 B2 = __ldg(reinterpret_cast<const float4*>(base + (c2 & ~3)) + 1);

    constexpr int M1 = (M0 + 2) & 3;

    float r0[5], r1[5], r2[5];
    #pragma unroll
    for (int i = 0; i < 5; i++) {
        r0[i] = comp(A0, B0, M0 + i);
        r1[i] = comp(A1, B1, M1 + i);
        r2[i] = comp(A2, B2, M0 + i);
    }

    float4 v0, v1;
    {
        float t0[4], t1[4], t2[4];
        #pragma unroll
        for (int i = 0; i < 4; i++) {
            t0[i] = r0[i] + wx * (r0[i + 1] - r0[i]);
            t1[i] = r1[i] + wx * (r1[i + 1] - r1[i]);
            t2[i] = r2[i] + wx * (r2[i + 1] - r2[i]);
        }
        v0.x = t0[0] + wy0 * (t1[0] - t0[0]);
        v0.y = t0[1] + wy0 * (t1[1] - t0[1]);
        v0.z = t0[2] + wy0 * (t1[2] - t0[2]);
        v0.w = t0[3] + wy0 * (t1[3] - t0[3]);
        v1.x = t1[0] + wy1 * (t2[0] - t1[0]);
        v1.y = t1[1] + wy1 * (t2[1] - t1[1]);
        v1.z = t1[2] + wy1 * (t2[2] - t1[2]);
        v1.w = t1[3] + wy1 * (t2[3] - t1[3]);
    }
    *reinterpret_cast<float4*>(o0 + 4 * tid) = v0;
    *reinterpret_cast<float4*>(o1 + 4 * tid) = v1;
}

__global__ __launch_bounds__(128) void extract_patches_kernel(
    const float* __restrict__ img,   // (B, 522, 522, 1)
    const float* __restrict__ pos,   // (B, 2)  [px, py]
    float* __restrict__ out)         // (B, 512, 512, 1)
{
    const int b   = blockIdx.z;
    const int y0  = blockIdx.y * 2;
    const int tid = threadIdx.x;

    const float px = __ldg(pos + 2 * b);
    const float py = __ldg(pos + 2 * b + 1);

    // Exact reference row arithmetic for both output rows.
    const float sy0  = (float)(y0 + 5) + py;
    const float yf0  = floorf(sy0);
    const float wy0  = sy0 - yf0;
    const int   Y    = (int)yf0;

    const float sy1  = (float)(y0 + 6) + py;
    const float yf1  = floorf(sy1);
    const float wy1  = sy1 - yf1;
    const int   Y2   = (int)yf1;

    const float s0   = 5.0f + px;
    const float x0f  = floorf(s0);
    const float wx   = s0 - x0f;
    const int   X0   = (int)x0f;

    const float* base = img + (size_t)b * (NPAD * NPAD);
    float* o0 = out + ((size_t)b * NOUT + y0) * NOUT;
    float* o1 = o0 + NOUT;

    const bool fast = (X0 >= 0) & (X0 <= 9) & (Y >= 0) & (Y <= NPAD - 3) & (Y2 == Y + 1);

    if (fast) {
        const int m = (2 * Y + X0) & 3;   // uniform across block (4*tid % 4 == 0)
        switch (m) {
        case 0:  fast_pair<0>(base, o0, o1, tid, Y, X0, wx, wy0, wy1); break;
        case 1:  fast_pair<1>(base, o0, o1, tid, Y, X0, wx, wy0, wy1); break;
        case 2:  fast_pair<2>(base, o0, o1, tid, Y, X0, wx, wy0, wy1); break;
        default: fast_pair<3>(base, o0, o1, tid, Y, X0, wx, wy0, wy1); break;
        }
    } else {
        // Exact per-pixel path with full predication (handles zero fill).
        #pragma unroll
        for (int r = 0; r < 2; r++) {
            const int   yy   = y0 + r;
            const float sy   = (float)(yy + 5) + py;
            const float yf   = floorf(sy);
            const float wyp  = sy - yf;
            const int   Yr   = (int)yf;
            const bool vy0 = ((unsigned)Yr       < (unsigned)NPAD);
            const bool vy1 = ((unsigned)(Yr + 1) < (unsigned)NPAD);
            const float* rr = base + (ptrdiff_t)Yr * NPAD;
            float* orow = out + ((size_t)b * NOUT + yy) * NOUT;
            #pragma unroll
            for (int i = 0; i < 4; i++) {
                const int   x    = 4 * tid + i;
                const float sx   = (float)(x + 5) + px;
                const float xf   = floorf(sx);
                const float wxp  = sx - xf;
                const int   X    = (int)xf;
                const bool vx0 = ((unsigned)X       < (unsigned)NPAD);
                const bool vx1 = ((unsigned)(X + 1) < (unsigned)NPAD);
                const float* p0 = rr + X;
                float g00 = 0.0f, g01 = 0.0f, g10 = 0.0f, g11 = 0.0f;
                if (vy0 && vx0) g00 = __ldg(p0);
                if (vy0 && vx1) g01 = __ldg(p0 + 1);
                if (vy1 && vx0) g10 = __ldg(p0 + NPAD);
                if (vy1 && vx1) g11 = __ldg(p0 + NPAD + 1);
                const float top = g00 + wxp * (g01 - g00);
                const float bot = g10 + wxp * (g11 - g10);
                orow[x] = top + wyp * (bot - top);
            }
        }
    }
}

extern "C" void kernel_launch(void* const* d_in, const int* in_sizes, int n_in,
                              void* d_out, int out_size)
{
    const float* img = (const float*)d_in[0];   // padded_obj: 256*522*522*1 f32
    const float* pos = (const float*)d_in[1];   // positions:  256*2 f32
    float* out = (float*)d_out;                 // 256*512*512*1 f32

    dim3 block(128, 1, 1);
    dim3 grid(1, NOUT / 2, B);                  // (1, 256, 256)
    extract_patches_kernel<<<grid, block>>>(img, pos, out);
}